// round 1
// baseline (speedup 1.0000x reference)
#include <cuda_runtime.h>
#include <math.h>
#include <stdint.h>

// ---------------- problem constants ----------------
#define Bx      16
#define Lx      64
#define Nx      1024
#define HAND    99
#define Jx      21
#define HIDD    512
#define NLAYERS 4
#define NHEADS  8
#define DHD     64
#define CATD    2273
#define SEQ     128          // 2*Lx
#define M1      (Bx*Lx)      // 1024 rows per hand
#define M2      (Bx*SEQ)     // 2048 transformer rows

// ---------------- scratch (single __device__ arena) ----------------
#define OFF_PCT   0
#define SZ_PCT    (M1*Nx*3)            // 3,145,728
#define OFF_PCN   (OFF_PCT + SZ_PCT)
#define SZ_PCN    (M1*Nx)              // 1,048,576
#define OFF_ATT   (OFF_PCN + SZ_PCN)
#define SZ_ATT    (2*M1*Jx*3)          // 129,024
#define OFF_CAT   (OFF_ATT + SZ_ATT)
#define SZ_CAT    (2*M1*CATD)          // 4,655,104
#define OFF_FC    (OFF_CAT + SZ_CAT)
#define SZ_FC     (2*M1*HIDD)          // 1,048,576
#define OFF_X     (OFF_FC + SZ_FC)
#define SZ_X      (M2*HIDD)
#define OFF_H     (OFF_X + SZ_X)
#define SZ_H      (M2*HIDD)
#define OFF_QKV   (OFF_H + SZ_H)
#define SZ_QKV    (M2*3*HIDD)
#define OFF_AO    (OFF_QKV + SZ_QKV)
#define SZ_AO     (M2*HIDD)
#define OFF_FF    (OFF_AO + SZ_AO)
#define SZ_FF     (M2*4*HIDD)
#define OFF_TMP   (OFF_FF + SZ_FF)
#define SZ_TMP    (M2*HIDD)
#define SCRATCH_TOTAL (OFF_TMP + SZ_TMP)

__device__ float g_scratch[SCRATCH_TOTAL];

// ---------------- rot6d + pc transform + norm ----------------
__global__ void transform_kernel(const float* __restrict__ x_obj,
                                 const float* __restrict__ pc,
                                 float* __restrict__ pct,
                                 float* __restrict__ pcn) {
    int bl = blockIdx.x;
    int b  = bl / Lx;
    const float* xo = x_obj + (size_t)bl * 10;
    float tx = xo[0], ty = xo[1], tz = xo[2];
    float a1x = xo[3], a1y = xo[4], a1z = xo[5];
    float a2x = xo[6], a2y = xo[7], a2z = xo[8];
    float n1 = sqrtf(a1x*a1x + a1y*a1y + a1z*a1z);
    float b1x = a1x/n1, b1y = a1y/n1, b1z = a1z/n1;
    float dd  = b1x*a2x + b1y*a2y + b1z*a2z;
    float b2x = a2x - dd*b1x, b2y = a2y - dd*b1y, b2z = a2z - dd*b1z;
    float n2 = sqrtf(b2x*b2x + b2y*b2y + b2z*b2z);
    b2x /= n2; b2y /= n2; b2z /= n2;
    float b3x = b1y*b2z - b1z*b2y;
    float b3y = b1z*b2x - b1x*b2z;
    float b3z = b1x*b2y - b1y*b2x;
    const float* pcb = pc + (size_t)b * Nx * 3;
    for (int n = threadIdx.x; n < Nx; n += blockDim.x) {
        float px = pcb[n*3+0], py = pcb[n*3+1], pz = pcb[n*3+2];
        float ox = b1x*px + b2x*py + b3x*pz + tx;
        float oy = b1y*px + b2y*py + b3y*pz + ty;
        float oz = b1z*px + b2z*py + b3z*pz + tz;
        float* o = pct + ((size_t)bl * Nx + n) * 3;
        o[0] = ox; o[1] = oy; o[2] = oz;
        pcn[(size_t)bl * Nx + n] = sqrtf(ox*ox + oy*oy + oz*oz);
    }
}

// ---------------- nearest-point attention map ----------------
// block per (bl, hand): 21 warps, one per joint; pc tile staged in smem.
__global__ void attmap_kernel(const float* __restrict__ jl,
                              const float* __restrict__ jr,
                              const float* __restrict__ pct,
                              float* __restrict__ att) {
    __shared__ float pcs[Nx*3];  // 48 KB
    int bl = blockIdx.x, hand = blockIdx.y;
    const float* src = pct + (size_t)bl * Nx * 3;
    for (int i = threadIdx.x; i < Nx*3; i += blockDim.x) pcs[i] = src[i];
    __syncthreads();
    int w = threadIdx.x >> 5, lane = threadIdx.x & 31;
    if (w >= Jx) return;
    const float* jp = (hand ? jr : jl) + ((size_t)bl * Jx + w) * 3;
    float jx = jp[0], jy = jp[1], jz = jp[2];
    float jj = jx*jx + jy*jy + jz*jz;
    float best = 3.4e38f; int bidx = Nx;
    for (int n = lane; n < Nx; n += 32) {
        float px = pcs[n*3+0], py = pcs[n*3+1], pz = pcs[n*3+2];
        float pp = px*px + py*py + pz*pz;
        float d2 = jj + pp - 2.f*(jx*px + jy*py + jz*pz);
        if (d2 < best || (d2 == best && n < bidx)) { best = d2; bidx = n; }
    }
    for (int o = 16; o; o >>= 1) {
        float ob = __shfl_down_sync(0xffffffffu, best, o);
        int   oi = __shfl_down_sync(0xffffffffu, bidx, o);
        if (ob < best || (ob == best && oi < bidx)) { best = ob; bidx = oi; }
    }
    if (lane == 0) {
        float cx = pcs[bidx*3+0], cy = pcs[bidx*3+1], cz = pcs[bidx*3+2];
        float dx = jx - cx, dy = jy - cy, dz = jz - cz;
        float* o = att + ((size_t)hand * M1 * Jx + (size_t)bl * Jx + w) * 3;
        o[0] = expf(-50.f * dx*dx);
        o[1] = expf(-50.f * dy*dy);
        o[2] = expf(-50.f * dz*dz);
    }
}

// ---------------- concat feature assembly ----------------
__global__ void buildcat_kernel(const float* __restrict__ xl, const float* __restrict__ xr,
                                const float* __restrict__ jl, const float* __restrict__ jr,
                                const float* __restrict__ mc, const float* __restrict__ pcn,
                                const float* __restrict__ att, float* __restrict__ cat) {
    int bl = blockIdx.x, hand = blockIdx.y;
    int b = bl / Lx;
    float* dst = cat + ((size_t)hand * M1 + bl) * CATD;
    const float* xh = hand ? xr : xl;
    const float* jh = hand ? jr : jl;
    for (int c = threadIdx.x; c < CATD; c += blockDim.x) {
        float v;
        if (c < 99)        v = xh[(size_t)bl * HAND + c];
        else if (c < 162)  v = jh[(size_t)bl * 63 + (c - 99)];
        else if (c < 1186) v = mc[(size_t)b * Nx + (c - 162)];
        else if (c < 2210) v = pcn[(size_t)bl * Nx + (c - 1186)];
        else               v = att[(size_t)hand * M1 * 63 + (size_t)bl * 63 + (c - 2210)];
        dst[c] = v;
    }
}

// ---------------- SGEMM 64x64x16, 4x4/thread ----------------
__global__ void sgemm64(const float* __restrict__ A, const float* __restrict__ Bw,
                        const float* __restrict__ bias, float* __restrict__ C,
                        int M, int N, int K, int flags) {
    __shared__ float As[16][65];
    __shared__ float Bs[16][65];
    int tid = threadIdx.x, tx = tid & 15, ty = tid >> 4;
    int row0 = blockIdx.y * 64, col0 = blockIdx.x * 64;
    float acc[4][4] = {};
    for (int k0 = 0; k0 < K; k0 += 16) {
        #pragma unroll
        for (int i = 0; i < 4; i++) {
            int idx = tid + i*256; int m = idx >> 4, kk = idx & 15;
            int gr = row0 + m, gk = k0 + kk;
            As[kk][m] = (gr < M && gk < K) ? A[(size_t)gr*K + gk] : 0.f;
        }
        #pragma unroll
        for (int i = 0; i < 4; i++) {
            int idx = tid + i*256; int kk = idx >> 6, n = idx & 63;
            int gk = k0 + kk, gc = col0 + n;
            Bs[kk][n] = (gk < K && gc < N) ? Bw[(size_t)gk*N + gc] : 0.f;
        }
        __syncthreads();
        #pragma unroll
        for (int kk = 0; kk < 16; kk++) {
            float a[4], b[4];
            #pragma unroll
            for (int i = 0; i < 4; i++) a[i] = As[kk][ty*4+i];
            #pragma unroll
            for (int j = 0; j < 4; j++) b[j] = Bs[kk][tx*4+j];
            #pragma unroll
            for (int i = 0; i < 4; i++)
                #pragma unroll
                for (int j = 0; j < 4; j++) acc[i][j] += a[i]*b[j];
        }
        __syncthreads();
    }
    #pragma unroll
    for (int i = 0; i < 4; i++) {
        int r = row0 + ty*4 + i; if (r >= M) continue;
        #pragma unroll
        for (int j = 0; j < 4; j++) {
            int c = col0 + tx*4 + j; if (c >= N) continue;
            float v = acc[i][j];
            if (flags & 1) v += bias[c];
            if (flags & 2) v = fmaxf(v, 0.f);
            C[(size_t)r*N + c] = v;
        }
    }
}

// ---------------- SGEMM 128x128x8, 8x8/thread ----------------
__global__ void sgemm128(const float* __restrict__ A, const float* __restrict__ Bw,
                         const float* __restrict__ bias, float* __restrict__ C,
                         int M, int N, int K, int flags) {
    __shared__ float As[8][132];
    __shared__ float Bs[8][132];
    int tid = threadIdx.x, tx = tid & 15, ty = tid >> 4;
    int row0 = blockIdx.y * 128, col0 = blockIdx.x * 128;
    float acc[8][8] = {};
    for (int k0 = 0; k0 < K; k0 += 8) {
        #pragma unroll
        for (int i = 0; i < 4; i++) {
            int idx = tid + i*256; int m = idx >> 3, kk = idx & 7;
            int gr = row0 + m, gk = k0 + kk;
            As[kk][m] = (gr < M && gk < K) ? A[(size_t)gr*K + gk] : 0.f;
        }
        #pragma unroll
        for (int i = 0; i < 4; i++) {
            int idx = tid + i*256; int kk = idx >> 7, n = idx & 127;
            int gk = k0 + kk, gc = col0 + n;
            Bs[kk][n] = (gk < K && gc < N) ? Bw[(size_t)gk*N + gc] : 0.f;
        }
        __syncthreads();
        #pragma unroll
        for (int kk = 0; kk < 8; kk++) {
            float a[8], b[8];
            #pragma unroll
            for (int i = 0; i < 8; i++) a[i] = As[kk][ty*8+i];
            #pragma unroll
            for (int j = 0; j < 8; j++) b[j] = Bs[kk][tx*8+j];
            #pragma unroll
            for (int i = 0; i < 8; i++)
                #pragma unroll
                for (int j = 0; j < 8; j++) acc[i][j] += a[i]*b[j];
        }
        __syncthreads();
    }
    #pragma unroll
    for (int i = 0; i < 8; i++) {
        int r = row0 + ty*8 + i; if (r >= M) continue;
        #pragma unroll
        for (int j = 0; j < 8; j++) {
            int c = col0 + tx*8 + j; if (c >= N) continue;
            float v = acc[i][j];
            if (flags & 1) v += bias[c];
            if (flags & 2) v = fmaxf(v, 0.f);
            C[(size_t)r*N + c] = v;
        }
    }
}

// ---------------- interleave L/R + positional encodings ----------------
__global__ void interleave_pe(const float* __restrict__ fl, const float* __restrict__ fr,
                              float* __restrict__ x) {
    int idx = blockIdx.x * blockDim.x + threadIdx.x;
    if (idx >= M2*HIDD) return;
    int d = idx & (HIDD - 1);
    int srow = idx >> 9;
    int s = srow & (SEQ - 1);
    int b = srow >> 7;
    int l = s >> 1, h = s & 1;
    const float* src = h ? fr : fl;
    float v = src[((size_t)(b*Lx + l)) * HIDD + d];
    int i2 = d & ~1;  // 2*(d/2)
    float div = expf((float)i2 * (-9.2103403719761836f / 512.f));
    float pl = (d & 1) ? cosf((float)l * div) : sinf((float)l * div);
    float pa = (d & 1) ? cosf((float)h * div) : sinf((float)h * div);
    x[idx] = v + pl + pa;
}

// ---------------- per-(b,h) attention ----------------
#define ATTN_SMEM ((2*SEQ*DHD + SEQ*129) * 4)
__global__ void attn_kernel(const float* __restrict__ qkv, float* __restrict__ out) {
    extern __shared__ float sm[];
    float* Ks = sm;                 // 128*64
    float* Vs = sm + SEQ*DHD;       // 128*64
    float* Ss = sm + 2*SEQ*DHD;     // 128*129 (padded)
    int b = blockIdx.x >> 3, h = blockIdx.x & 7;
    int i = threadIdx.x;
    for (int idx = i; idx < SEQ*DHD; idx += blockDim.x) {
        int s = idx >> 6, d = idx & 63;
        size_t base = ((size_t)(b*SEQ + s)) * 1536 + h*64 + d;
        Ks[idx] = qkv[base + 512];
        Vs[idx] = qkv[base + 1024];
    }
    float q[DHD];
    {
        size_t base = ((size_t)(b*SEQ + i)) * 1536 + h*64;
        #pragma unroll
        for (int d = 0; d < DHD; d++) q[d] = qkv[base + d];
    }
    __syncthreads();
    float m = -3.4e38f;
    float* srow = Ss + i*129;
    for (int k = 0; k < SEQ; k++) {
        float s = 0.f;
        #pragma unroll
        for (int d = 0; d < DHD; d++) s += q[d] * Ks[k*64 + d];
        s *= 0.125f;
        srow[k] = s;
        m = fmaxf(m, s);
    }
    float sum = 0.f;
    for (int k = 0; k < SEQ; k++) {
        float e = expf(srow[k] - m);
        srow[k] = e; sum += e;
    }
    float inv = 1.f / sum;
    size_t obase = ((size_t)(b*SEQ + i)) * HIDD + h*64;
    for (int d0 = 0; d0 < DHD; d0 += 16) {
        float acc[16] = {};
        for (int k = 0; k < SEQ; k++) {
            float p = srow[k];
            #pragma unroll
            for (int dd = 0; dd < 16; dd++) acc[dd] += p * Vs[k*64 + d0 + dd];
        }
        #pragma unroll
        for (int dd = 0; dd < 16; dd++) out[obase + d0 + dd] = acc[dd] * inv;
    }
}

// ---------------- residual + layernorm ----------------
__global__ void addln_kernel(const float* __restrict__ a, const float* __restrict__ r,
                             const float* __restrict__ g, const float* __restrict__ be,
                             float* __restrict__ out) {
    int row = blockIdx.x;
    int t = threadIdx.x;                 // 128 threads, 4 elems each
    const float* pa = a + (size_t)row * HIDD;
    const float* pr = r + (size_t)row * HIDD;
    float v[4];
    #pragma unroll
    for (int i = 0; i < 4; i++) { int c = t + i*128; v[i] = pa[c] + pr[c]; }
    float s = v[0] + v[1] + v[2] + v[3];
    __shared__ float sh[4];
    for (int o = 16; o; o >>= 1) s += __shfl_down_sync(0xffffffffu, s, o);
    int lane = t & 31, w = t >> 5;
    if (lane == 0) sh[w] = s;
    __syncthreads();
    float mu = (sh[0] + sh[1] + sh[2] + sh[3]) * (1.f / HIDD);
    float qv = 0.f;
    #pragma unroll
    for (int i = 0; i < 4; i++) { float d = v[i] - mu; qv += d*d; }
    __syncthreads();
    for (int o = 16; o; o >>= 1) qv += __shfl_down_sync(0xffffffffu, qv, o);
    if (lane == 0) sh[w] = qv;
    __syncthreads();
    float var = (sh[0] + sh[1] + sh[2] + sh[3]) * (1.f / HIDD);
    float inv = rsqrtf(var + 1e-5f);
    float* po = out + (size_t)row * HIDD;
    #pragma unroll
    for (int i = 0; i < 4; i++) { int c = t + i*128; po[c] = (v[i] - mu)*inv*g[c] + be[c]; }
}

// ---------------- deinterleave even/odd rows ----------------
__global__ void deinterleave(const float* __restrict__ x,
                             float* __restrict__ fl, float* __restrict__ fr) {
    int idx = blockIdx.x * blockDim.x + threadIdx.x;
    if (idx >= M1*HIDD) return;
    int d = idx & 511; int bl = idx >> 9;
    int b = bl >> 6, l = bl & 63;
    fl[idx] = x[((size_t)(b*SEQ + 2*l    )) * HIDD + d];
    fr[idx] = x[((size_t)(b*SEQ + 2*l + 1)) * HIDD + d];
}

// ---------------- launch ----------------
extern "C" void kernel_launch(void* const* d_in, const int* in_sizes, int n_in,
                              void* d_out, int out_size) {
    const float* x_lhand     = (const float*)d_in[0];
    const float* x_rhand     = (const float*)d_in[1];
    const float* j_lhand     = (const float*)d_in[2];
    const float* j_rhand     = (const float*)d_in[3];
    const float* m_contact   = (const float*)d_in[4];
    const float* x_obj       = (const float*)d_in[5];
    const float* point_cloud = (const float*)d_in[6];
    const float* fc_lw  = (const float*)d_in[7];
    const float* fc_lb  = (const float*)d_in[8];
    const float* fc_rw  = (const float*)d_in[9];
    const float* fc_rb  = (const float*)d_in[10];
    const float* out_lw = (const float*)d_in[11];
    const float* out_lb = (const float*)d_in[12];
    const float* out_rw = (const float*)d_in[13];
    const float* out_rb = (const float*)d_in[14];
    const float* Wqkv   = (const float*)d_in[15];
    const float* bqkv   = (const float*)d_in[16];
    const float* Wo     = (const float*)d_in[17];
    const float* bo     = (const float*)d_in[18];
    const float* W1     = (const float*)d_in[19];
    const float* b1f    = (const float*)d_in[20];
    const float* W2     = (const float*)d_in[21];
    const float* b2f    = (const float*)d_in[22];
    const float* ln1_g  = (const float*)d_in[23];
    const float* ln1_b  = (const float*)d_in[24];
    const float* ln2_g  = (const float*)d_in[25];
    const float* ln2_b  = (const float*)d_in[26];
    float* out = (float*)d_out;

    float* base = nullptr;
    cudaGetSymbolAddress((void**)&base, g_scratch);
    float* pct = base + OFF_PCT;
    float* pcn = base + OFF_PCN;
    float* att = base + OFF_ATT;
    float* cat = base + OFF_CAT;
    float* fcb = base + OFF_FC;
    float* x   = base + OFF_X;
    float* h   = base + OFF_H;
    float* qkv = base + OFF_QKV;
    float* ao  = base + OFF_AO;
    float* ff  = base + OFF_FF;
    float* tmp = base + OFF_TMP;

    cudaFuncSetAttribute(attn_kernel, cudaFuncAttributeMaxDynamicSharedMemorySize, ATTN_SMEM);

    transform_kernel<<<M1, 256>>>(x_obj, point_cloud, pct, pcn);
    attmap_kernel<<<dim3(M1, 2), Jx*32>>>(j_lhand, j_rhand, pct, att);
    buildcat_kernel<<<dim3(M1, 2), 256>>>(x_lhand, x_rhand, j_lhand, j_rhand,
                                          m_contact, pcn, att, cat);

    // input projections: [1024 x 2273] @ [2273 x 512]
    sgemm64<<<dim3(8, 16), 256>>>(cat,                fc_lw, fc_lb, fcb,           M1, HIDD, CATD, 1);
    sgemm64<<<dim3(8, 16), 256>>>(cat + (size_t)M1*CATD, fc_rw, fc_rb, fcb + M1*HIDD, M1, HIDD, CATD, 1);
    interleave_pe<<<(M2*HIDD + 255)/256, 256>>>(fcb, fcb + M1*HIDD, x);

    for (int l = 0; l < NLAYERS; l++) {
        sgemm128<<<dim3(12, 16), 256>>>(x, Wqkv + (size_t)l*HIDD*3*HIDD, bqkv + (size_t)l*3*HIDD,
                                        qkv, M2, 3*HIDD, HIDD, 1);
        attn_kernel<<<Bx*NHEADS, SEQ, ATTN_SMEM>>>(qkv, ao);
        sgemm64<<<dim3(8, 32), 256>>>(ao, Wo + (size_t)l*HIDD*HIDD, bo + (size_t)l*HIDD,
                                      tmp, M2, HIDD, HIDD, 1);
        addln_kernel<<<M2, 128>>>(x, tmp, ln1_g + (size_t)l*HIDD, ln1_b + (size_t)l*HIDD, h);
        sgemm128<<<dim3(16, 16), 256>>>(h, W1 + (size_t)l*HIDD*4*HIDD, b1f + (size_t)l*4*HIDD,
                                        ff, M2, 4*HIDD, HIDD, 1 | 2);
        sgemm64<<<dim3(8, 32), 256>>>(ff, W2 + (size_t)l*4*HIDD*HIDD, b2f + (size_t)l*HIDD,
                                      tmp, M2, HIDD, 4*HIDD, 1);
        addln_kernel<<<M2, 128>>>(h, tmp, ln2_g + (size_t)l*HIDD, ln2_b + (size_t)l*HIDD, x);
    }

    deinterleave<<<(M1*HIDD + 255)/256, 256>>>(x, fcb, fcb + M1*HIDD);
    sgemm64<<<dim3(2, 16), 256>>>(fcb,           out_lw, out_lb, out,             M1, HAND, HIDD, 1);
    sgemm64<<<dim3(2, 16), 256>>>(fcb + M1*HIDD, out_rw, out_rb, out + M1*HAND,   M1, HAND, HIDD, 1);
}

// round 2
// speedup vs baseline: 1.2689x; 1.2689x over previous
#include <cuda_runtime.h>
#include <math.h>
#include <stdint.h>

// ---------------- problem constants ----------------
#define Bx      16
#define Lx      64
#define Nx      1024
#define HAND    99
#define Jx      21
#define HIDD    512
#define NLAYERS 4
#define NHEADS  8
#define DHD     64
#define CATD    2273
#define SEQ     128          // 2*Lx
#define M1      (Bx*Lx)      // 1024 rows per hand
#define M2      (Bx*SEQ)     // 2048 transformer rows

// ---------------- scratch (single __device__ arena) ----------------
#define OFF_PCT   0
#define SZ_PCT    (M1*Nx*3)
#define OFF_PCN   (OFF_PCT + SZ_PCT)
#define SZ_PCN    (M1*Nx)
#define OFF_ATT   (OFF_PCN + SZ_PCN)
#define SZ_ATT    (2*M1*Jx*3)
#define OFF_CAT   (OFF_ATT + SZ_ATT)
#define SZ_CAT    (2*M1*CATD)
#define OFF_FC    (OFF_CAT + SZ_CAT)
#define SZ_FC     (2*M1*HIDD)
#define OFF_X     (OFF_FC + SZ_FC)
#define SZ_X      (M2*HIDD)
#define OFF_H     (OFF_X + SZ_X)
#define SZ_H      (M2*HIDD)
#define OFF_QKV   (OFF_H + SZ_H)
#define SZ_QKV    (M2*3*HIDD)
#define OFF_AO    (OFF_QKV + SZ_QKV)
#define SZ_AO     (M2*HIDD)
#define OFF_FF    (OFF_AO + SZ_AO)
#define SZ_FF     (M2*4*HIDD)
#define OFF_TMP   (OFF_FF + SZ_FF)
#define SZ_TMP    (M2*HIDD)
#define SCRATCH_TOTAL (OFF_TMP + SZ_TMP)

__device__ float g_scratch[SCRATCH_TOTAL];

// ---------------- rot6d + pc transform + norm ----------------
__global__ void transform_kernel(const float* __restrict__ x_obj,
                                 const float* __restrict__ pc,
                                 float* __restrict__ pct,
                                 float* __restrict__ pcn) {
    int bl = blockIdx.x;
    int b  = bl / Lx;
    const float* xo = x_obj + (size_t)bl * 10;
    float tx = xo[0], ty = xo[1], tz = xo[2];
    float a1x = xo[3], a1y = xo[4], a1z = xo[5];
    float a2x = xo[6], a2y = xo[7], a2z = xo[8];
    float n1 = sqrtf(a1x*a1x + a1y*a1y + a1z*a1z);
    float b1x = a1x/n1, b1y = a1y/n1, b1z = a1z/n1;
    float dd  = b1x*a2x + b1y*a2y + b1z*a2z;
    float b2x = a2x - dd*b1x, b2y = a2y - dd*b1y, b2z = a2z - dd*b1z;
    float n2 = sqrtf(b2x*b2x + b2y*b2y + b2z*b2z);
    b2x /= n2; b2y /= n2; b2z /= n2;
    float b3x = b1y*b2z - b1z*b2y;
    float b3y = b1z*b2x - b1x*b2z;
    float b3z = b1x*b2y - b1y*b2x;
    const float* pcb = pc + (size_t)b * Nx * 3;
    for (int n = threadIdx.x; n < Nx; n += blockDim.x) {
        float px = pcb[n*3+0], py = pcb[n*3+1], pz = pcb[n*3+2];
        float ox = b1x*px + b2x*py + b3x*pz + tx;
        float oy = b1y*px + b2y*py + b3y*pz + ty;
        float oz = b1z*px + b2z*py + b3z*pz + tz;
        float* o = pct + ((size_t)bl * Nx + n) * 3;
        o[0] = ox; o[1] = oy; o[2] = oz;
        pcn[(size_t)bl * Nx + n] = sqrtf(ox*ox + oy*oy + oz*oz);
    }
}

// ---------------- nearest-point attention map ----------------
__global__ void attmap_kernel(const float* __restrict__ jl,
                              const float* __restrict__ jr,
                              const float* __restrict__ pct,
                              float* __restrict__ att) {
    __shared__ float pcs[Nx*3];
    int bl = blockIdx.x, hand = blockIdx.y;
    const float* src = pct + (size_t)bl * Nx * 3;
    for (int i = threadIdx.x; i < Nx*3; i += blockDim.x) pcs[i] = src[i];
    __syncthreads();
    int w = threadIdx.x >> 5, lane = threadIdx.x & 31;
    if (w >= Jx) return;
    const float* jp = (hand ? jr : jl) + ((size_t)bl * Jx + w) * 3;
    float jx = jp[0], jy = jp[1], jz = jp[2];
    float jj = jx*jx + jy*jy + jz*jz;
    float best = 3.4e38f; int bidx = Nx;
    for (int n = lane; n < Nx; n += 32) {
        float px = pcs[n*3+0], py = pcs[n*3+1], pz = pcs[n*3+2];
        float pp = px*px + py*py + pz*pz;
        float d2 = jj + pp - 2.f*(jx*px + jy*py + jz*pz);
        if (d2 < best || (d2 == best && n < bidx)) { best = d2; bidx = n; }
    }
    for (int o = 16; o; o >>= 1) {
        float ob = __shfl_down_sync(0xffffffffu, best, o);
        int   oi = __shfl_down_sync(0xffffffffu, bidx, o);
        if (ob < best || (ob == best && oi < bidx)) { best = ob; bidx = oi; }
    }
    if (lane == 0) {
        float cx = pcs[bidx*3+0], cy = pcs[bidx*3+1], cz = pcs[bidx*3+2];
        float dx = jx - cx, dy = jy - cy, dz = jz - cz;
        float* o = att + ((size_t)hand * M1 * Jx + (size_t)bl * Jx + w) * 3;
        o[0] = expf(-50.f * dx*dx);
        o[1] = expf(-50.f * dy*dy);
        o[2] = expf(-50.f * dz*dz);
    }
}

// ---------------- concat feature assembly ----------------
__global__ void buildcat_kernel(const float* __restrict__ xl, const float* __restrict__ xr,
                                const float* __restrict__ jl, const float* __restrict__ jr,
                                const float* __restrict__ mc, const float* __restrict__ pcn,
                                const float* __restrict__ att, float* __restrict__ cat) {
    int bl = blockIdx.x, hand = blockIdx.y;
    int b = bl / Lx;
    float* dst = cat + ((size_t)hand * M1 + bl) * CATD;
    const float* xh = hand ? xr : xl;
    const float* jh = hand ? jr : jl;
    for (int c = threadIdx.x; c < CATD; c += blockDim.x) {
        float v;
        if (c < 99)        v = xh[(size_t)bl * HAND + c];
        else if (c < 162)  v = jh[(size_t)bl * 63 + (c - 99)];
        else if (c < 1186) v = mc[(size_t)b * Nx + (c - 162)];
        else if (c < 2210) v = pcn[(size_t)bl * Nx + (c - 1186)];
        else               v = att[(size_t)hand * M1 * 63 + (size_t)bl * 63 + (c - 2210)];
        dst[c] = v;
    }
}

// ---------------- tf32 helpers ----------------
__device__ __forceinline__ uint32_t f32_tf32(float x) {
    uint32_t r;
    asm("cvt.rna.tf32.f32 %0, %1;" : "=r"(r) : "f"(x));
    return r;
}
__device__ __forceinline__ void split_tf32(float v, float& h, float& l) {
    uint32_t hb = f32_tf32(v);
    h = __uint_as_float(hb);
    l = __uint_as_float(f32_tf32(v - h));
}
__device__ __forceinline__ void mma_tf32(float* c, const uint32_t* a, const uint32_t* b) {
    asm("mma.sync.aligned.m16n8k8.row.col.f32.tf32.tf32.f32 "
        "{%0,%1,%2,%3}, {%4,%5,%6,%7}, {%8,%9}, {%0,%1,%2,%3};\n"
        : "+f"(c[0]), "+f"(c[1]), "+f"(c[2]), "+f"(c[3])
        : "r"(a[0]), "r"(a[1]), "r"(a[2]), "r"(a[3]), "r"(b[0]), "r"(b[1]));
}

// ---------------- 3xTF32 tensor-core GEMM ----------------
// Block tile 128x128x32, 8 warps (4m x 2n), warp tile 32x64 (m16n8k8 frags).
// A staged [m][k] stride 36 (hi+lo); B staged [k][n] stride 136 (hi+lo).
// Optional row-split B/bias selection for the fused two-hand fc projection.
#define TG_AS  36
#define TG_BS  136
#define TG_ASZ (128*TG_AS)   // 4608 floats
#define TG_BSZ (32*TG_BS)    // 4352 floats
#define TG_SMEM ((2*TG_ASZ + 2*TG_BSZ) * 4)  // 71680 bytes

__global__ void __launch_bounds__(256, 2)
tgemm(const float* __restrict__ A,
      const float* __restrict__ B1, const float* __restrict__ bias1,
      const float* __restrict__ B2, const float* __restrict__ bias2,
      float* __restrict__ C, int M, int N, int K, int flags, int rowsplit) {
    extern __shared__ float sm[];
    float* Ah = sm;
    float* Al = Ah + TG_ASZ;
    float* Bh = Al + TG_ASZ;
    float* Bl = Bh + TG_BSZ;

    int tid = threadIdx.x;
    int row0 = blockIdx.y * 128, col0 = blockIdx.x * 128;
    const float* Bw   = (row0 >= rowsplit) ? B2 : B1;
    const float* bias = (row0 >= rowsplit) ? bias2 : bias1;

    int warp = tid >> 5, lane = tid & 31;
    int wm = warp & 3, wn = warp >> 2;
    int m0 = wm * 32, n0 = wn * 64;
    int g = lane >> 2, t = lane & 3;

    float acc[2][8][4];
    #pragma unroll
    for (int mi = 0; mi < 2; mi++)
        #pragma unroll
        for (int ni = 0; ni < 8; ni++)
            #pragma unroll
            for (int j = 0; j < 4; j++) acc[mi][ni][j] = 0.f;

    const bool vecA = ((K & 3) == 0);

    for (int k0 = 0; k0 < K; k0 += 32) {
        __syncthreads();
        // ---- stage A (hi/lo) ----
        if (vecA) {
            #pragma unroll
            for (int i = 0; i < 4; i++) {
                int idx = tid + i*256;
                int m = idx >> 3, kq = idx & 7;
                int gk = k0 + kq*4;
                float4 v = make_float4(0.f,0.f,0.f,0.f);
                if (gk + 3 < K)
                    v = *(const float4*)(A + (size_t)(row0+m)*K + gk);
                float4 h, l;
                split_tf32(v.x, h.x, l.x); split_tf32(v.y, h.y, l.y);
                split_tf32(v.z, h.z, l.z); split_tf32(v.w, h.w, l.w);
                *(float4*)(Ah + m*TG_AS + kq*4) = h;
                *(float4*)(Al + m*TG_AS + kq*4) = l;
            }
        } else {
            #pragma unroll
            for (int i = 0; i < 16; i++) {
                int idx = tid + i*256;
                int m = idx >> 5, kk = idx & 31;
                int gk = k0 + kk;
                float v = (gk < K) ? A[(size_t)(row0+m)*K + gk] : 0.f;
                float h, l;
                split_tf32(v, h, l);
                Ah[m*TG_AS + kk] = h;
                Al[m*TG_AS + kk] = l;
            }
        }
        // ---- stage B (hi/lo) ----
        #pragma unroll
        for (int i = 0; i < 4; i++) {
            int idx = tid + i*256;
            int kk = idx >> 5, nq = idx & 31;
            int gk = k0 + kk;
            float4 v = make_float4(0.f,0.f,0.f,0.f);
            if (gk < K)
                v = *(const float4*)(Bw + (size_t)gk*N + col0 + nq*4);
            float4 h, l;
            split_tf32(v.x, h.x, l.x); split_tf32(v.y, h.y, l.y);
            split_tf32(v.z, h.z, l.z); split_tf32(v.w, h.w, l.w);
            *(float4*)(Bh + kk*TG_BS + nq*4) = h;
            *(float4*)(Bl + kk*TG_BS + nq*4) = l;
        }
        __syncthreads();
        // ---- compute ----
        #pragma unroll
        for (int ks = 0; ks < 4; ks++) {
            int kc = ks*8 + t;
            uint32_t ahr[2][4], alr[2][4];
            #pragma unroll
            for (int mi = 0; mi < 2; mi++) {
                int mr = m0 + mi*16 + g;
                ahr[mi][0] = __float_as_uint(Ah[mr*TG_AS + kc]);
                ahr[mi][1] = __float_as_uint(Ah[(mr+8)*TG_AS + kc]);
                ahr[mi][2] = __float_as_uint(Ah[mr*TG_AS + kc + 4]);
                ahr[mi][3] = __float_as_uint(Ah[(mr+8)*TG_AS + kc + 4]);
                alr[mi][0] = __float_as_uint(Al[mr*TG_AS + kc]);
                alr[mi][1] = __float_as_uint(Al[(mr+8)*TG_AS + kc]);
                alr[mi][2] = __float_as_uint(Al[mr*TG_AS + kc + 4]);
                alr[mi][3] = __float_as_uint(Al[(mr+8)*TG_AS + kc + 4]);
            }
            #pragma unroll
            for (int ni = 0; ni < 8; ni++) {
                int nc = n0 + ni*8 + g;
                uint32_t bhr[2], blr[2];
                bhr[0] = __float_as_uint(Bh[kc*TG_BS + nc]);
                bhr[1] = __float_as_uint(Bh[(kc+4)*TG_BS + nc]);
                blr[0] = __float_as_uint(Bl[kc*TG_BS + nc]);
                blr[1] = __float_as_uint(Bl[(kc+4)*TG_BS + nc]);
                #pragma unroll
                for (int mi = 0; mi < 2; mi++) {
                    mma_tf32(acc[mi][ni], ahr[mi], bhr);
                    mma_tf32(acc[mi][ni], alr[mi], bhr);
                    mma_tf32(acc[mi][ni], ahr[mi], blr);
                }
            }
        }
    }
    // ---- epilogue ----
    #pragma unroll
    for (int mi = 0; mi < 2; mi++) {
        int r = row0 + m0 + mi*16 + g;
        #pragma unroll
        for (int ni = 0; ni < 8; ni++) {
            int c = col0 + n0 + ni*8 + 2*t;
            float v0 = acc[mi][ni][0], v1 = acc[mi][ni][1];
            float v2 = acc[mi][ni][2], v3 = acc[mi][ni][3];
            if (flags & 1) {
                float b0v = bias[c], b1v = bias[c+1];
                v0 += b0v; v1 += b1v; v2 += b0v; v3 += b1v;
            }
            if (flags & 2) {
                v0 = fmaxf(v0, 0.f); v1 = fmaxf(v1, 0.f);
                v2 = fmaxf(v2, 0.f); v3 = fmaxf(v3, 0.f);
            }
            C[(size_t)r*N + c]       = v0;
            C[(size_t)r*N + c + 1]   = v1;
            C[(size_t)(r+8)*N + c]   = v2;
            C[(size_t)(r+8)*N + c+1] = v3;
        }
    }
}

// ---------------- SGEMM 64x64x16 (small output heads only) ----------------
__global__ void sgemm64(const float* __restrict__ A, const float* __restrict__ Bw,
                        const float* __restrict__ bias, float* __restrict__ C,
                        int M, int N, int K, int flags) {
    __shared__ float As[16][65];
    __shared__ float Bs[16][65];
    int tid = threadIdx.x, tx = tid & 15, ty = tid >> 4;
    int row0 = blockIdx.y * 64, col0 = blockIdx.x * 64;
    float acc[4][4] = {};
    for (int k0 = 0; k0 < K; k0 += 16) {
        #pragma unroll
        for (int i = 0; i < 4; i++) {
            int idx = tid + i*256; int m = idx >> 4, kk = idx & 15;
            int gr = row0 + m, gk = k0 + kk;
            As[kk][m] = (gr < M && gk < K) ? A[(size_t)gr*K + gk] : 0.f;
        }
        #pragma unroll
        for (int i = 0; i < 4; i++) {
            int idx = tid + i*256; int kk = idx >> 6, n = idx & 63;
            int gk = k0 + kk, gc = col0 + n;
            Bs[kk][n] = (gk < K && gc < N) ? Bw[(size_t)gk*N + gc] : 0.f;
        }
        __syncthreads();
        #pragma unroll
        for (int kk = 0; kk < 16; kk++) {
            float a[4], b[4];
            #pragma unroll
            for (int i = 0; i < 4; i++) a[i] = As[kk][ty*4+i];
            #pragma unroll
            for (int j = 0; j < 4; j++) b[j] = Bs[kk][tx*4+j];
            #pragma unroll
            for (int i = 0; i < 4; i++)
                #pragma unroll
                for (int j = 0; j < 4; j++) acc[i][j] += a[i]*b[j];
        }
        __syncthreads();
    }
    #pragma unroll
    for (int i = 0; i < 4; i++) {
        int r = row0 + ty*4 + i; if (r >= M) continue;
        #pragma unroll
        for (int j = 0; j < 4; j++) {
            int c = col0 + tx*4 + j; if (c >= N) continue;
            float v = acc[i][j];
            if (flags & 1) v += bias[c];
            if (flags & 2) v = fmaxf(v, 0.f);
            C[(size_t)r*N + c] = v;
        }
    }
}

// ---------------- interleave L/R + positional encodings ----------------
__global__ void interleave_pe(const float* __restrict__ fl, const float* __restrict__ fr,
                              float* __restrict__ x) {
    int idx = blockIdx.x * blockDim.x + threadIdx.x;
    if (idx >= M2*HIDD) return;
    int d = idx & (HIDD - 1);
    int srow = idx >> 9;
    int s = srow & (SEQ - 1);
    int b = srow >> 7;
    int l = s >> 1, h = s & 1;
    const float* src = h ? fr : fl;
    float v = src[((size_t)(b*Lx + l)) * HIDD + d];
    int i2 = d & ~1;
    float div = expf((float)i2 * (-9.2103403719761836f / 512.f));
    float pl = (d & 1) ? cosf((float)l * div) : sinf((float)l * div);
    float pa = (d & 1) ? cosf((float)h * div) : sinf((float)h * div);
    x[idx] = v + pl + pa;
}

// ---------------- per-(b,h) attention ----------------
#define ATTN_SMEM ((2*SEQ*DHD + SEQ*129) * 4)
__global__ void attn_kernel(const float* __restrict__ qkv, float* __restrict__ out) {
    extern __shared__ float sm[];
    float* Ks = sm;
    float* Vs = sm + SEQ*DHD;
    float* Ss = sm + 2*SEQ*DHD;
    int b = blockIdx.x >> 3, h = blockIdx.x & 7;
    int i = threadIdx.x;
    for (int idx = i; idx < SEQ*DHD; idx += blockDim.x) {
        int s = idx >> 6, d = idx & 63;
        size_t base = ((size_t)(b*SEQ + s)) * 1536 + h*64 + d;
        Ks[idx] = qkv[base + 512];
        Vs[idx] = qkv[base + 1024];
    }
    float q[DHD];
    {
        size_t base = ((size_t)(b*SEQ + i)) * 1536 + h*64;
        #pragma unroll
        for (int d = 0; d < DHD; d++) q[d] = qkv[base + d];
    }
    __syncthreads();
    float m = -3.4e38f;
    float* srow = Ss + i*129;
    for (int k = 0; k < SEQ; k++) {
        float s = 0.f;
        #pragma unroll
        for (int d = 0; d < DHD; d++) s += q[d] * Ks[k*64 + d];
        s *= 0.125f;
        srow[k] = s;
        m = fmaxf(m, s);
    }
    float sum = 0.f;
    for (int k = 0; k < SEQ; k++) {
        float e = expf(srow[k] - m);
        srow[k] = e; sum += e;
    }
    float inv = 1.f / sum;
    size_t obase = ((size_t)(b*SEQ + i)) * HIDD + h*64;
    for (int d0 = 0; d0 < DHD; d0 += 16) {
        float acc[16] = {};
        for (int k = 0; k < SEQ; k++) {
            float p = srow[k];
            #pragma unroll
            for (int dd = 0; dd < 16; dd++) acc[dd] += p * Vs[k*64 + d0 + dd];
        }
        #pragma unroll
        for (int dd = 0; dd < 16; dd++) out[obase + d0 + dd] = acc[dd] * inv;
    }
}

// ---------------- residual + layernorm ----------------
__global__ void addln_kernel(const float* __restrict__ a, const float* __restrict__ r,
                             const float* __restrict__ g, const float* __restrict__ be,
                             float* __restrict__ out) {
    int row = blockIdx.x;
    int t = threadIdx.x;
    const float* pa = a + (size_t)row * HIDD;
    const float* pr = r + (size_t)row * HIDD;
    float v[4];
    #pragma unroll
    for (int i = 0; i < 4; i++) { int c = t + i*128; v[i] = pa[c] + pr[c]; }
    float s = v[0] + v[1] + v[2] + v[3];
    __shared__ float sh[4];
    for (int o = 16; o; o >>= 1) s += __shfl_down_sync(0xffffffffu, s, o);
    int lane = t & 31, w = t >> 5;
    if (lane == 0) sh[w] = s;
    __syncthreads();
    float mu = (sh[0] + sh[1] + sh[2] + sh[3]) * (1.f / HIDD);
    float qv = 0.f;
    #pragma unroll
    for (int i = 0; i < 4; i++) { float d = v[i] - mu; qv += d*d; }
    __syncthreads();
    for (int o = 16; o; o >>= 1) qv += __shfl_down_sync(0xffffffffu, qv, o);
    if (lane == 0) sh[w] = qv;
    __syncthreads();
    float var = (sh[0] + sh[1] + sh[2] + sh[3]) * (1.f / HIDD);
    float inv = rsqrtf(var + 1e-5f);
    float* po = out + (size_t)row * HIDD;
    #pragma unroll
    for (int i = 0; i < 4; i++) { int c = t + i*128; po[c] = (v[i] - mu)*inv*g[c] + be[c]; }
}

// ---------------- deinterleave even/odd rows ----------------
__global__ void deinterleave(const float* __restrict__ x,
                             float* __restrict__ fl, float* __restrict__ fr) {
    int idx = blockIdx.x * blockDim.x + threadIdx.x;
    if (idx >= M1*HIDD) return;
    int d = idx & 511; int bl = idx >> 9;
    int b = bl >> 6, l = bl & 63;
    fl[idx] = x[((size_t)(b*SEQ + 2*l    )) * HIDD + d];
    fr[idx] = x[((size_t)(b*SEQ + 2*l + 1)) * HIDD + d];
}

// ---------------- launch ----------------
extern "C" void kernel_launch(void* const* d_in, const int* in_sizes, int n_in,
                              void* d_out, int out_size) {
    const float* x_lhand     = (const float*)d_in[0];
    const float* x_rhand     = (const float*)d_in[1];
    const float* j_lhand     = (const float*)d_in[2];
    const float* j_rhand     = (const float*)d_in[3];
    const float* m_contact   = (const float*)d_in[4];
    const float* x_obj       = (const float*)d_in[5];
    const float* point_cloud = (const float*)d_in[6];
    const float* fc_lw  = (const float*)d_in[7];
    const float* fc_lb  = (const float*)d_in[8];
    const float* fc_rw  = (const float*)d_in[9];
    const float* fc_rb  = (const float*)d_in[10];
    const float* out_lw = (const float*)d_in[11];
    const float* out_lb = (const float*)d_in[12];
    const float* out_rw = (const float*)d_in[13];
    const float* out_rb = (const float*)d_in[14];
    const float* Wqkv   = (const float*)d_in[15];
    const float* bqkv   = (const float*)d_in[16];
    const float* Wo     = (const float*)d_in[17];
    const float* bo     = (const float*)d_in[18];
    const float* W1     = (const float*)d_in[19];
    const float* b1f    = (const float*)d_in[20];
    const float* W2     = (const float*)d_in[21];
    const float* b2f    = (const float*)d_in[22];
    const float* ln1_g  = (const float*)d_in[23];
    const float* ln1_b  = (const float*)d_in[24];
    const float* ln2_g  = (const float*)d_in[25];
    const float* ln2_b  = (const float*)d_in[26];
    float* out = (float*)d_out;

    float* base = nullptr;
    cudaGetSymbolAddress((void**)&base, g_scratch);
    float* pct = base + OFF_PCT;
    float* pcn = base + OFF_PCN;
    float* att = base + OFF_ATT;
    float* cat = base + OFF_CAT;
    float* fcb = base + OFF_FC;
    float* x   = base + OFF_X;
    float* h   = base + OFF_H;
    float* qkv = base + OFF_QKV;
    float* ao  = base + OFF_AO;
    float* ff  = base + OFF_FF;
    float* tmp = base + OFF_TMP;

    cudaFuncSetAttribute(attn_kernel, cudaFuncAttributeMaxDynamicSharedMemorySize, ATTN_SMEM);
    cudaFuncSetAttribute(tgemm, cudaFuncAttributeMaxDynamicSharedMemorySize, TG_SMEM);

    transform_kernel<<<M1, 256>>>(x_obj, point_cloud, pct, pcn);
    attmap_kernel<<<dim3(M1, 2), Jx*32>>>(j_lhand, j_rhand, pct, att);
    buildcat_kernel<<<dim3(M1, 2), 256>>>(x_lhand, x_rhand, j_lhand, j_rhand,
                                          m_contact, pcn, att, cat);

    // fused both-hand input projection: [2048 x 2273] @ [2273 x 512], row-split weights
    tgemm<<<dim3(4, 16), 256, TG_SMEM>>>(cat, fc_lw, fc_lb, fc_rw, fc_rb,
                                         fcb, 2*M1, HIDD, CATD, 1, M1);
    interleave_pe<<<(M2*HIDD + 255)/256, 256>>>(fcb, fcb + M1*HIDD, x);

    for (int l = 0; l < NLAYERS; l++) {
        const float* wq = Wqkv + (size_t)l*HIDD*3*HIDD;
        const float* bq = bqkv + (size_t)l*3*HIDD;
        tgemm<<<dim3(12, 16), 256, TG_SMEM>>>(x, wq, bq, wq, bq,
                                              qkv, M2, 3*HIDD, HIDD, 1, M2);
        attn_kernel<<<Bx*NHEADS, SEQ, ATTN_SMEM>>>(qkv, ao);
        const float* wo = Wo + (size_t)l*HIDD*HIDD;
        const float* bob = bo + (size_t)l*HIDD;
        tgemm<<<dim3(4, 16), 256, TG_SMEM>>>(ao, wo, bob, wo, bob,
                                             tmp, M2, HIDD, HIDD, 1, M2);
        addln_kernel<<<M2, 128>>>(x, tmp, ln1_g + (size_t)l*HIDD, ln1_b + (size_t)l*HIDD, h);
        const float* w1 = W1 + (size_t)l*HIDD*4*HIDD;
        const float* b1 = b1f + (size_t)l*4*HIDD;
        tgemm<<<dim3(16, 16), 256, TG_SMEM>>>(h, w1, b1, w1, b1,
                                              ff, M2, 4*HIDD, HIDD, 1 | 2, M2);
        const float* w2 = W2 + (size_t)l*4*HIDD*HIDD;
        const float* b2 = b2f + (size_t)l*HIDD;
        tgemm<<<dim3(4, 16), 256, TG_SMEM>>>(ff, w2, b2, w2, b2,
                                             tmp, M2, HIDD, 4*HIDD, 1, M2);
        addln_kernel<<<M2, 128>>>(h, tmp, ln2_g + (size_t)l*HIDD, ln2_b + (size_t)l*HIDD, x);
    }

    deinterleave<<<(M1*HIDD + 255)/256, 256>>>(x, fcb, fcb + M1*HIDD);
    sgemm64<<<dim3(2, 16), 256>>>(fcb,           out_lw, out_lb, out,           M1, HAND, HIDD, 1);
    sgemm64<<<dim3(2, 16), 256>>>(fcb + M1*HIDD, out_rw, out_rb, out + M1*HAND, M1, HAND, HIDD, 1);
}

// round 3
// speedup vs baseline: 1.6215x; 1.2778x over previous
#include <cuda_runtime.h>
#include <math.h>
#include <stdint.h>

// ---------------- problem constants ----------------
#define Bx      16
#define Lx      64
#define Nx      1024
#define HAND    99
#define Jx      21
#define HIDD    512
#define NLAYERS 4
#define NHEADS  8
#define DHD     64
#define CATD    2273
#define SEQ     128          // 2*Lx
#define M1      (Bx*Lx)      // 1024 rows per hand
#define M2      (Bx*SEQ)     // 2048 transformer rows

// ---------------- scratch (single __device__ arena) ----------------
#define OFF_PCT   0
#define SZ_PCT    (M1*Nx*3)
#define OFF_PCN   (OFF_PCT + SZ_PCT)
#define SZ_PCN    (M1*Nx)
#define OFF_ATT   (OFF_PCN + SZ_PCN)
#define SZ_ATT    (2*M1*Jx*3)
#define OFF_CAT   (OFF_ATT + SZ_ATT)
#define SZ_CAT    (2*M1*CATD)
#define OFF_FC    (OFF_CAT + SZ_CAT)
#define SZ_FC     (2*M1*HIDD)
#define OFF_X     (OFF_FC + SZ_FC)
#define SZ_X      (M2*HIDD)
#define OFF_H     (OFF_X + SZ_X)
#define SZ_H      (M2*HIDD)
#define OFF_QKV   (OFF_H + SZ_H)
#define SZ_QKV    (M2*3*HIDD)
#define OFF_AO    (OFF_QKV + SZ_QKV)
#define SZ_AO     (M2*HIDD)
#define OFF_FF    (OFF_AO + SZ_AO)
#define SZ_FF     (M2*4*HIDD)
#define OFF_TMP   (OFF_FF + SZ_FF)
#define SZ_TMP    (M2*HIDD)
#define SCRATCH_TOTAL (OFF_TMP + SZ_TMP)

__device__ float g_scratch[SCRATCH_TOTAL];

// ---------------- rot6d + pc transform + norm ----------------
__global__ void transform_kernel(const float* __restrict__ x_obj,
                                 const float* __restrict__ pc,
                                 float* __restrict__ pct,
                                 float* __restrict__ pcn) {
    int bl = blockIdx.x;
    int b  = bl / Lx;
    const float* xo = x_obj + (size_t)bl * 10;
    float tx = xo[0], ty = xo[1], tz = xo[2];
    float a1x = xo[3], a1y = xo[4], a1z = xo[5];
    float a2x = xo[6], a2y = xo[7], a2z = xo[8];
    float n1 = sqrtf(a1x*a1x + a1y*a1y + a1z*a1z);
    float b1x = a1x/n1, b1y = a1y/n1, b1z = a1z/n1;
    float dd  = b1x*a2x + b1y*a2y + b1z*a2z;
    float b2x = a2x - dd*b1x, b2y = a2y - dd*b1y, b2z = a2z - dd*b1z;
    float n2 = sqrtf(b2x*b2x + b2y*b2y + b2z*b2z);
    b2x /= n2; b2y /= n2; b2z /= n2;
    float b3x = b1y*b2z - b1z*b2y;
    float b3y = b1z*b2x - b1x*b2z;
    float b3z = b1x*b2y - b1y*b2x;
    const float* pcb = pc + (size_t)b * Nx * 3;
    for (int n = threadIdx.x; n < Nx; n += blockDim.x) {
        float px = pcb[n*3+0], py = pcb[n*3+1], pz = pcb[n*3+2];
        float ox = b1x*px + b2x*py + b3x*pz + tx;
        float oy = b1y*px + b2y*py + b3y*pz + ty;
        float oz = b1z*px + b2z*py + b3z*pz + tz;
        float* o = pct + ((size_t)bl * Nx + n) * 3;
        o[0] = ox; o[1] = oy; o[2] = oz;
        pcn[(size_t)bl * Nx + n] = sqrtf(ox*ox + oy*oy + oz*oz);
    }
}

// ---------------- nearest-point attention map ----------------
__global__ void attmap_kernel(const float* __restrict__ jl,
                              const float* __restrict__ jr,
                              const float* __restrict__ pct,
                              float* __restrict__ att) {
    __shared__ float pcs[Nx*3];
    int bl = blockIdx.x, hand = blockIdx.y;
    const float* src = pct + (size_t)bl * Nx * 3;
    for (int i = threadIdx.x; i < Nx*3; i += blockDim.x) pcs[i] = src[i];
    __syncthreads();
    int w = threadIdx.x >> 5, lane = threadIdx.x & 31;
    if (w >= Jx) return;
    const float* jp = (hand ? jr : jl) + ((size_t)bl * Jx + w) * 3;
    float jx = jp[0], jy = jp[1], jz = jp[2];
    float jj = jx*jx + jy*jy + jz*jz;
    float best = 3.4e38f; int bidx = Nx;
    for (int n = lane; n < Nx; n += 32) {
        float px = pcs[n*3+0], py = pcs[n*3+1], pz = pcs[n*3+2];
        float pp = px*px + py*py + pz*pz;
        float d2 = jj + pp - 2.f*(jx*px + jy*py + jz*pz);
        if (d2 < best || (d2 == best && n < bidx)) { best = d2; bidx = n; }
    }
    for (int o = 16; o; o >>= 1) {
        float ob = __shfl_down_sync(0xffffffffu, best, o);
        int   oi = __shfl_down_sync(0xffffffffu, bidx, o);
        if (ob < best || (ob == best && oi < bidx)) { best = ob; bidx = oi; }
    }
    if (lane == 0) {
        float cx = pcs[bidx*3+0], cy = pcs[bidx*3+1], cz = pcs[bidx*3+2];
        float dx = jx - cx, dy = jy - cy, dz = jz - cz;
        float* o = att + ((size_t)hand * M1 * Jx + (size_t)bl * Jx + w) * 3;
        o[0] = expf(-50.f * dx*dx);
        o[1] = expf(-50.f * dy*dy);
        o[2] = expf(-50.f * dz*dz);
    }
}

// ---------------- concat feature assembly ----------------
__global__ void buildcat_kernel(const float* __restrict__ xl, const float* __restrict__ xr,
                                const float* __restrict__ jl, const float* __restrict__ jr,
                                const float* __restrict__ mc, const float* __restrict__ pcn,
                                const float* __restrict__ att, float* __restrict__ cat) {
    int bl = blockIdx.x, hand = blockIdx.y;
    int b = bl / Lx;
    float* dst = cat + ((size_t)hand * M1 + bl) * CATD;
    const float* xh = hand ? xr : xl;
    const float* jh = hand ? jr : jl;
    for (int c = threadIdx.x; c < CATD; c += blockDim.x) {
        float v;
        if (c < 99)        v = xh[(size_t)bl * HAND + c];
        else if (c < 162)  v = jh[(size_t)bl * 63 + (c - 99)];
        else if (c < 1186) v = mc[(size_t)b * Nx + (c - 162)];
        else if (c < 2210) v = pcn[(size_t)bl * Nx + (c - 1186)];
        else               v = att[(size_t)hand * M1 * 63 + (size_t)bl * 63 + (c - 2210)];
        dst[c] = v;
    }
}

// ---------------- tf32 helpers ----------------
__device__ __forceinline__ uint32_t f32_tf32(float x) {
    uint32_t r;
    asm("cvt.rna.tf32.f32 %0, %1;" : "=r"(r) : "f"(x));
    return r;
}
__device__ __forceinline__ void split_tf32(float v, float& h, float& l) {
    uint32_t hb = f32_tf32(v);
    h = __uint_as_float(hb);
    l = __uint_as_float(f32_tf32(v - h));
}
__device__ __forceinline__ void mma_tf32(float* c, const uint32_t* a, const uint32_t* b) {
    asm("mma.sync.aligned.m16n8k8.row.col.f32.tf32.tf32.f32 "
        "{%0,%1,%2,%3}, {%4,%5,%6,%7}, {%8,%9}, {%0,%1,%2,%3};\n"
        : "+f"(c[0]), "+f"(c[1]), "+f"(c[2]), "+f"(c[3])
        : "r"(a[0]), "r"(a[1]), "r"(a[2]), "r"(a[3]), "r"(b[0]), "r"(b[1]));
}

// ---------------- 3xTF32 tensor-core GEMM, double-buffered ----------------
// Block tile 128x64x16, 8 warps (4m x 2n), warp tile 32x32.
// A staged [m][k] stride 20 (hi+lo); B staged [k][n] stride 72 (hi+lo).
// Two smem stages; next tile's globals prefetched to regs before compute.
#define TBM 128
#define TBN 64
#define TBK 16
#define TAS 20
#define TBS 72
#define TASZ (TBM*TAS)        // 2560 floats per copy
#define TBSZ (TBK*TBS)        // 1152 floats per copy
#define TG_SMEM ((4*TASZ + 4*TBSZ) * 4)  // 2 stages * (hi+lo) = 59392 B

__global__ void __launch_bounds__(256, 2)
tgemm(const float* __restrict__ A,
      const float* __restrict__ B1, const float* __restrict__ bias1,
      const float* __restrict__ B2, const float* __restrict__ bias2,
      float* __restrict__ C, int M, int N, int K, int flags, int rowsplit) {
    extern __shared__ float sm[];
    float* Ah = sm;                    // [2][TASZ]
    float* Al = Ah + 2*TASZ;
    float* Bh = Al + 2*TASZ;           // [2][TBSZ]
    float* Bl = Bh + 2*TBSZ;

    int tid = threadIdx.x;
    int row0 = blockIdx.y * TBM, col0 = blockIdx.x * TBN;
    const float* Bw   = (row0 >= rowsplit) ? B2 : B1;
    const float* bias = (row0 >= rowsplit) ? bias2 : bias1;

    int warp = tid >> 5, lane = tid & 31;
    int wm = warp & 3, wn = warp >> 2;
    int m0 = wm * 32, n0 = wn * 32;
    int g = lane >> 2, t = lane & 3;

    float acc[2][4][4];
    #pragma unroll
    for (int mi = 0; mi < 2; mi++)
        #pragma unroll
        for (int ni = 0; ni < 4; ni++)
            #pragma unroll
            for (int j = 0; j < 4; j++) acc[mi][ni][j] = 0.f;

    const bool vecA = ((K & 3) == 0);
    const int ntiles = (K + TBK - 1) / TBK;

    // prefetch registers
    float4 pa0, pa1;            // vec path (2 float4 per thread)
    float  pas[8];              // scalar path
    float4 pbv;

    // index helpers (constant per thread)
    const int av_m0 = (tid)       >> 2, av_k0 = ((tid)       & 3) * 4;
    const int av_m1 = (tid + 256) >> 2, av_k1 = ((tid + 256) & 3) * 4;
    const int b_kk  = tid >> 4,  b_nq = tid & 15;

    auto load_tile = [&](int ti) {
        int k0 = ti * TBK;
        if (vecA) {
            pa0 = *(const float4*)(A + (size_t)(row0 + av_m0)*K + k0 + av_k0);
            pa1 = *(const float4*)(A + (size_t)(row0 + av_m1)*K + k0 + av_k1);
        } else {
            #pragma unroll
            for (int i = 0; i < 8; i++) {
                int idx = tid + i*256;
                int m = idx >> 4, kk = idx & 15;
                int gk = k0 + kk;
                pas[i] = (gk < K) ? A[(size_t)(row0 + m)*K + gk] : 0.f;
            }
        }
        int gk = k0 + b_kk;
        if (gk < K) pbv = *(const float4*)(Bw + (size_t)gk*N + col0 + b_nq*4);
        else        pbv = make_float4(0.f, 0.f, 0.f, 0.f);
    };

    auto store_tile = [&](int st) {
        float* AhS = Ah + st*TASZ; float* AlS = Al + st*TASZ;
        float* BhS = Bh + st*TBSZ; float* BlS = Bl + st*TBSZ;
        if (vecA) {
            float4 h, l;
            split_tf32(pa0.x, h.x, l.x); split_tf32(pa0.y, h.y, l.y);
            split_tf32(pa0.z, h.z, l.z); split_tf32(pa0.w, h.w, l.w);
            *(float4*)(AhS + av_m0*TAS + av_k0) = h;
            *(float4*)(AlS + av_m0*TAS + av_k0) = l;
            split_tf32(pa1.x, h.x, l.x); split_tf32(pa1.y, h.y, l.y);
            split_tf32(pa1.z, h.z, l.z); split_tf32(pa1.w, h.w, l.w);
            *(float4*)(AhS + av_m1*TAS + av_k1) = h;
            *(float4*)(AlS + av_m1*TAS + av_k1) = l;
        } else {
            #pragma unroll
            for (int i = 0; i < 8; i++) {
                int idx = tid + i*256;
                int m = idx >> 4, kk = idx & 15;
                float h, l;
                split_tf32(pas[i], h, l);
                AhS[m*TAS + kk] = h;
                AlS[m*TAS + kk] = l;
            }
        }
        float4 h, l;
        split_tf32(pbv.x, h.x, l.x); split_tf32(pbv.y, h.y, l.y);
        split_tf32(pbv.z, h.z, l.z); split_tf32(pbv.w, h.w, l.w);
        *(float4*)(BhS + b_kk*TBS + b_nq*4) = h;
        *(float4*)(BlS + b_kk*TBS + b_nq*4) = l;
    };

    load_tile(0);
    store_tile(0);
    __syncthreads();

    for (int ti = 0; ti < ntiles; ti++) {
        int st = ti & 1;
        if (ti + 1 < ntiles) load_tile(ti + 1);

        const float* AhS = Ah + st*TASZ; const float* AlS = Al + st*TASZ;
        const float* BhS = Bh + st*TBSZ; const float* BlS = Bl + st*TBSZ;
        #pragma unroll
        for (int ks = 0; ks < 2; ks++) {
            int kc = ks*8 + t;
            uint32_t ahr[2][4], alr[2][4];
            #pragma unroll
            for (int mi = 0; mi < 2; mi++) {
                int mr = m0 + mi*16 + g;
                ahr[mi][0] = __float_as_uint(AhS[mr*TAS + kc]);
                ahr[mi][1] = __float_as_uint(AhS[(mr+8)*TAS + kc]);
                ahr[mi][2] = __float_as_uint(AhS[mr*TAS + kc + 4]);
                ahr[mi][3] = __float_as_uint(AhS[(mr+8)*TAS + kc + 4]);
                alr[mi][0] = __float_as_uint(AlS[mr*TAS + kc]);
                alr[mi][1] = __float_as_uint(AlS[(mr+8)*TAS + kc]);
                alr[mi][2] = __float_as_uint(AlS[mr*TAS + kc + 4]);
                alr[mi][3] = __float_as_uint(AlS[(mr+8)*TAS + kc + 4]);
            }
            #pragma unroll
            for (int ni = 0; ni < 4; ni++) {
                int nc = n0 + ni*8 + g;
                uint32_t bhr[2], blr[2];
                bhr[0] = __float_as_uint(BhS[kc*TBS + nc]);
                bhr[1] = __float_as_uint(BhS[(kc+4)*TBS + nc]);
                blr[0] = __float_as_uint(BlS[kc*TBS + nc]);
                blr[1] = __float_as_uint(BlS[(kc+4)*TBS + nc]);
                #pragma unroll
                for (int mi = 0; mi < 2; mi++) {
                    mma_tf32(acc[mi][ni], ahr[mi], bhr);
                    mma_tf32(acc[mi][ni], alr[mi], bhr);
                    mma_tf32(acc[mi][ni], ahr[mi], blr);
                }
            }
        }
        if (ti + 1 < ntiles) store_tile((ti + 1) & 1);
        __syncthreads();
    }

    // ---- epilogue ----
    #pragma unroll
    for (int mi = 0; mi < 2; mi++) {
        int r = row0 + m0 + mi*16 + g;
        #pragma unroll
        for (int ni = 0; ni < 4; ni++) {
            int c = col0 + n0 + ni*8 + 2*t;
            float v0 = acc[mi][ni][0], v1 = acc[mi][ni][1];
            float v2 = acc[mi][ni][2], v3 = acc[mi][ni][3];
            if (flags & 1) {
                float b0v = bias[c], b1v = bias[c+1];
                v0 += b0v; v1 += b1v; v2 += b0v; v3 += b1v;
            }
            if (flags & 2) {
                v0 = fmaxf(v0, 0.f); v1 = fmaxf(v1, 0.f);
                v2 = fmaxf(v2, 0.f); v3 = fmaxf(v3, 0.f);
            }
            C[(size_t)r*N + c]       = v0;
            C[(size_t)r*N + c + 1]   = v1;
            C[(size_t)(r+8)*N + c]   = v2;
            C[(size_t)(r+8)*N + c+1] = v3;
        }
    }
}

// ---------------- SGEMM 64x64x16 (small output heads only) ----------------
__global__ void sgemm64(const float* __restrict__ A, const float* __restrict__ Bw,
                        const float* __restrict__ bias, float* __restrict__ C,
                        int M, int N, int K, int flags) {
    __shared__ float As[16][65];
    __shared__ float Bs[16][65];
    int tid = threadIdx.x, tx = tid & 15, ty = tid >> 4;
    int row0 = blockIdx.y * 64, col0 = blockIdx.x * 64;
    float acc[4][4] = {};
    for (int k0 = 0; k0 < K; k0 += 16) {
        #pragma unroll
        for (int i = 0; i < 4; i++) {
            int idx = tid + i*256; int m = idx >> 4, kk = idx & 15;
            int gr = row0 + m, gk = k0 + kk;
            As[kk][m] = (gr < M && gk < K) ? A[(size_t)gr*K + gk] : 0.f;
        }
        #pragma unroll
        for (int i = 0; i < 4; i++) {
            int idx = tid + i*256; int kk = idx >> 6, n = idx & 63;
            int gk = k0 + kk, gc = col0 + n;
            Bs[kk][n] = (gk < K && gc < N) ? Bw[(size_t)gk*N + gc] : 0.f;
        }
        __syncthreads();
        #pragma unroll
        for (int kk = 0; kk < 16; kk++) {
            float a[4], b[4];
            #pragma unroll
            for (int i = 0; i < 4; i++) a[i] = As[kk][ty*4+i];
            #pragma unroll
            for (int j = 0; j < 4; j++) b[j] = Bs[kk][tx*4+j];
            #pragma unroll
            for (int i = 0; i < 4; i++)
                #pragma unroll
                for (int j = 0; j < 4; j++) acc[i][j] += a[i]*b[j];
        }
        __syncthreads();
    }
    #pragma unroll
    for (int i = 0; i < 4; i++) {
        int r = row0 + ty*4 + i; if (r >= M) continue;
        #pragma unroll
        for (int j = 0; j < 4; j++) {
            int c = col0 + tx*4 + j; if (c >= N) continue;
            float v = acc[i][j];
            if (flags & 1) v += bias[c];
            if (flags & 2) v = fmaxf(v, 0.f);
            C[(size_t)r*N + c] = v;
        }
    }
}

// ---------------- interleave L/R + positional encodings ----------------
__global__ void interleave_pe(const float* __restrict__ fl, const float* __restrict__ fr,
                              float* __restrict__ x) {
    int idx = blockIdx.x * blockDim.x + threadIdx.x;
    if (idx >= M2*HIDD) return;
    int d = idx & (HIDD - 1);
    int srow = idx >> 9;
    int s = srow & (SEQ - 1);
    int b = srow >> 7;
    int l = s >> 1, h = s & 1;
    const float* src = h ? fr : fl;
    float v = src[((size_t)(b*Lx + l)) * HIDD + d];
    int i2 = d & ~1;
    float div = expf((float)i2 * (-9.2103403719761836f / 512.f));
    float pl = (d & 1) ? cosf((float)l * div) : sinf((float)l * div);
    float pa = (d & 1) ? cosf((float)h * div) : sinf((float)h * div);
    x[idx] = v + pl + pa;
}

// ---------------- per-(b,h) attention ----------------
#define ATTN_SMEM ((2*SEQ*DHD + SEQ*129) * 4)
__global__ void attn_kernel(const float* __restrict__ qkv, float* __restrict__ out) {
    extern __shared__ float sm[];
    float* Ks = sm;
    float* Vs = sm + SEQ*DHD;
    float* Ss = sm + 2*SEQ*DHD;
    int b = blockIdx.x >> 3, h = blockIdx.x & 7;
    int i = threadIdx.x;
    for (int idx = i; idx < SEQ*DHD; idx += blockDim.x) {
        int s = idx >> 6, d = idx & 63;
        size_t base = ((size_t)(b*SEQ + s)) * 1536 + h*64 + d;
        Ks[idx] = qkv[base + 512];
        Vs[idx] = qkv[base + 1024];
    }
    float q[DHD];
    {
        size_t base = ((size_t)(b*SEQ + i)) * 1536 + h*64;
        #pragma unroll
        for (int d = 0; d < DHD; d++) q[d] = qkv[base + d];
    }
    __syncthreads();
    float m = -3.4e38f;
    float* srow = Ss + i*129;
    for (int k = 0; k < SEQ; k++) {
        float s = 0.f;
        #pragma unroll
        for (int d = 0; d < DHD; d++) s += q[d] * Ks[k*64 + d];
        s *= 0.125f;
        srow[k] = s;
        m = fmaxf(m, s);
    }
    float sum = 0.f;
    for (int k = 0; k < SEQ; k++) {
        float e = expf(srow[k] - m);
        srow[k] = e; sum += e;
    }
    float inv = 1.f / sum;
    size_t obase = ((size_t)(b*SEQ + i)) * HIDD + h*64;
    for (int d0 = 0; d0 < DHD; d0 += 16) {
        float acc[16] = {};
        for (int k = 0; k < SEQ; k++) {
            float p = srow[k];
            #pragma unroll
            for (int dd = 0; dd < 16; dd++) acc[dd] += p * Vs[k*64 + d0 + dd];
        }
        #pragma unroll
        for (int dd = 0; dd < 16; dd++) out[obase + d0 + dd] = acc[dd] * inv;
    }
}

// ---------------- residual + layernorm ----------------
__global__ void addln_kernel(const float* __restrict__ a, const float* __restrict__ r,
                             const float* __restrict__ g, const float* __restrict__ be,
                             float* __restrict__ out) {
    int row = blockIdx.x;
    int t = threadIdx.x;
    const float* pa = a + (size_t)row * HIDD;
    const float* pr = r + (size_t)row * HIDD;
    float v[4];
    #pragma unroll
    for (int i = 0; i < 4; i++) { int c = t + i*128; v[i] = pa[c] + pr[c]; }
    float s = v[0] + v[1] + v[2] + v[3];
    __shared__ float sh[4];
    for (int o = 16; o; o >>= 1) s += __shfl_down_sync(0xffffffffu, s, o);
    int lane = t & 31, w = t >> 5;
    if (lane == 0) sh[w] = s;
    __syncthreads();
    float mu = (sh[0] + sh[1] + sh[2] + sh[3]) * (1.f / HIDD);
    float qv = 0.f;
    #pragma unroll
    for (int i = 0; i < 4; i++) { float d = v[i] - mu; qv += d*d; }
    __syncthreads();
    for (int o = 16; o; o >>= 1) qv += __shfl_down_sync(0xffffffffu, qv, o);
    if (lane == 0) sh[w] = qv;
    __syncthreads();
    float var = (sh[0] + sh[1] + sh[2] + sh[3]) * (1.f / HIDD);
    float inv = rsqrtf(var + 1e-5f);
    float* po = out + (size_t)row * HIDD;
    #pragma unroll
    for (int i = 0; i < 4; i++) { int c = t + i*128; po[c] = (v[i] - mu)*inv*g[c] + be[c]; }
}

// ---------------- deinterleave even/odd rows ----------------
__global__ void deinterleave(const float* __restrict__ x,
                             float* __restrict__ fl, float* __restrict__ fr) {
    int idx = blockIdx.x * blockDim.x + threadIdx.x;
    if (idx >= M1*HIDD) return;
    int d = idx & 511; int bl = idx >> 9;
    int b = bl >> 6, l = bl & 63;
    fl[idx] = x[((size_t)(b*SEQ + 2*l    )) * HIDD + d];
    fr[idx] = x[((size_t)(b*SEQ + 2*l + 1)) * HIDD + d];
}

// ---------------- launch ----------------
extern "C" void kernel_launch(void* const* d_in, const int* in_sizes, int n_in,
                              void* d_out, int out_size) {
    const float* x_lhand     = (const float*)d_in[0];
    const float* x_rhand     = (const float*)d_in[1];
    const float* j_lhand     = (const float*)d_in[2];
    const float* j_rhand     = (const float*)d_in[3];
    const float* m_contact   = (const float*)d_in[4];
    const float* x_obj       = (const float*)d_in[5];
    const float* point_cloud = (const float*)d_in[6];
    const float* fc_lw  = (const float*)d_in[7];
    const float* fc_lb  = (const float*)d_in[8];
    const float* fc_rw  = (const float*)d_in[9];
    const float* fc_rb  = (const float*)d_in[10];
    const float* out_lw = (const float*)d_in[11];
    const float* out_lb = (const float*)d_in[12];
    const float* out_rw = (const float*)d_in[13];
    const float* out_rb = (const float*)d_in[14];
    const float* Wqkv   = (const float*)d_in[15];
    const float* bqkv   = (const float*)d_in[16];
    const float* Wo     = (const float*)d_in[17];
    const float* bo     = (const float*)d_in[18];
    const float* W1     = (const float*)d_in[19];
    const float* b1f    = (const float*)d_in[20];
    const float* W2     = (const float*)d_in[21];
    const float* b2f    = (const float*)d_in[22];
    const float* ln1_g  = (const float*)d_in[23];
    const float* ln1_b  = (const float*)d_in[24];
    const float* ln2_g  = (const float*)d_in[25];
    const float* ln2_b  = (const float*)d_in[26];
    float* out = (float*)d_out;

    float* base = nullptr;
    cudaGetSymbolAddress((void**)&base, g_scratch);
    float* pct = base + OFF_PCT;
    float* pcn = base + OFF_PCN;
    float* att = base + OFF_ATT;
    float* cat = base + OFF_CAT;
    float* fcb = base + OFF_FC;
    float* x   = base + OFF_X;
    float* h   = base + OFF_H;
    float* qkv = base + OFF_QKV;
    float* ao  = base + OFF_AO;
    float* ff  = base + OFF_FF;
    float* tmp = base + OFF_TMP;

    cudaFuncSetAttribute(attn_kernel, cudaFuncAttributeMaxDynamicSharedMemorySize, ATTN_SMEM);
    cudaFuncSetAttribute(tgemm, cudaFuncAttributeMaxDynamicSharedMemorySize, TG_SMEM);

    transform_kernel<<<M1, 256>>>(x_obj, point_cloud, pct, pcn);
    attmap_kernel<<<dim3(M1, 2), Jx*32>>>(j_lhand, j_rhand, pct, att);
    buildcat_kernel<<<dim3(M1, 2), 256>>>(x_lhand, x_rhand, j_lhand, j_rhand,
                                          m_contact, pcn, att, cat);

    // fused both-hand input projection: [2048 x 2273] @ [2273 x 512], row-split weights
    tgemm<<<dim3(8, 16), 256, TG_SMEM>>>(cat, fc_lw, fc_lb, fc_rw, fc_rb,
                                         fcb, 2*M1, HIDD, CATD, 1, M1);
    interleave_pe<<<(M2*HIDD + 255)/256, 256>>>(fcb, fcb + M1*HIDD, x);

    for (int l = 0; l < NLAYERS; l++) {
        const float* wq = Wqkv + (size_t)l*HIDD*3*HIDD;
        const float* bq = bqkv + (size_t)l*3*HIDD;
        tgemm<<<dim3(24, 16), 256, TG_SMEM>>>(x, wq, bq, wq, bq,
                                              qkv, M2, 3*HIDD, HIDD, 1, M2);
        attn_kernel<<<Bx*NHEADS, SEQ, ATTN_SMEM>>>(qkv, ao);
        const float* wo = Wo + (size_t)l*HIDD*HIDD;
        const float* bob = bo + (size_t)l*HIDD;
        tgemm<<<dim3(8, 16), 256, TG_SMEM>>>(ao, wo, bob, wo, bob,
                                             tmp, M2, HIDD, HIDD, 1, M2);
        addln_kernel<<<M2, 128>>>(x, tmp, ln1_g + (size_t)l*HIDD, ln1_b + (size_t)l*HIDD, h);
        const float* w1 = W1 + (size_t)l*HIDD*4*HIDD;
        const float* b1 = b1f + (size_t)l*4*HIDD;
        tgemm<<<dim3(32, 16), 256, TG_SMEM>>>(h, w1, b1, w1, b1,
                                              ff, M2, 4*HIDD, HIDD, 1 | 2, M2);
        const float* w2 = W2 + (size_t)l*4*HIDD*HIDD;
        const float* b2 = b2f + (size_t)l*HIDD;
        tgemm<<<dim3(8, 16), 256, TG_SMEM>>>(ff, w2, b2, w2, b2,
                                             tmp, M2, HIDD, 4*HIDD, 1, M2);
        addln_kernel<<<M2, 128>>>(h, tmp, ln2_g + (size_t)l*HIDD, ln2_b + (size_t)l*HIDD, x);
    }

    deinterleave<<<(M1*HIDD + 255)/256, 256>>>(x, fcb, fcb + M1*HIDD);
    sgemm64<<<dim3(2, 16), 256>>>(fcb,           out_lw, out_lb, out,           M1, HAND, HIDD, 1);
    sgemm64<<<dim3(2, 16), 256>>>(fcb + M1*HIDD, out_rw, out_rb, out + M1*HAND, M1, HAND, HIDD, 1);
}